// round 5
// baseline (speedup 1.0000x reference)
#include <cuda_runtime.h>
#include <cuda_bf16.h>
#include <math.h>

#define N_QUBITS 16
#define N_LAYERS 3
#define N_STATES 65536
#define BATCH 256

// 64 MB state scratch (real amplitudes; imaginary parts are identically zero).
__device__ float g_state[(size_t)BATCH * N_STATES];
// Per (batch, layer, qubit) 2x2 real gate matrices: m00,m01,m10,m11
__device__ float g_M[BATCH * N_LAYERS * N_QUBITS * 4];
// Per (layer, q) CNOT mixing probability p = sigmoid(ent)
__device__ float g_p[N_LAYERS * (N_QUBITS - 1)];

// XOR swizzle so every smem access phase is bank-conflict-free.
#define PHYS(i) ((i) ^ (((i) >> 5) & 31))

// ---------------------------------------------------------------------------
// Prep: MLP -> h, then gate matrices M and CNOT probabilities p.
// ---------------------------------------------------------------------------
__global__ void prep_kernel(const float* __restrict__ X,
                            const float* __restrict__ rot,
                            const float* __restrict__ ent,
                            const float* __restrict__ W1,
                            const float* __restrict__ b1,
                            const float* __restrict__ W2,
                            const float* __restrict__ b2) {
    int b = blockIdx.x;
    int t = threadIdx.x;  // 128 threads
    __shared__ float sx[100];
    __shared__ float sh[64];
    __shared__ float shq[16];

    if (t < 100) sx[t] = X[b * 100 + t];
    __syncthreads();

    if (t < 64) {
        float acc = b1[t];
        #pragma unroll 4
        for (int k = 0; k < 100; k++) acc = fmaf(sx[k], W1[k * 64 + t], acc);
        sh[t] = fmaxf(acc, 0.0f);
    }
    __syncthreads();

    if (t < 16) {
        float acc = b2[t];
        #pragma unroll
        for (int j = 0; j < 64; j++) acc = fmaf(sh[j], W2[j * 16 + t], acc);
        shq[t] = tanhf(acc);
    }
    __syncthreads();

    if (t < N_LAYERS * N_QUBITS) {  // 48
        int layer = t / N_QUBITS, q = t % N_QUBITS;
        float hv = shq[q];
        float c[3], s[3];
        #pragma unroll
        for (int i = 0; i < 3; i++) {
            float ang = rot[(layer * N_QUBITS + q) * 3 + i] * hv;
            sincosf(0.5f * ang, &s[i], &c[i]);
        }
        float* m = g_M + ((b * N_LAYERS + layer) * N_QUBITS + q) * 4;
        m[0] =  c[0] * c[1] * c[2];   // m00 = cx*cy*cz
        m[1] = -s[0] * s[1] * s[2];   // m01 = -sx*sy*sz
        m[2] =  s[0] * s[1] * c[2];   // m10 = sx*sy*cz
        m[3] =  c[0] * c[1] * s[2];   // m11 = cx*cy*sz
    }
    if (b == 0 && t < N_LAYERS * (N_QUBITS - 1)) {  // 45
        g_p[t] = 1.0f / (1.0f + expf(-ent[t]));
    }
}

// ---------------------------------------------------------------------------
// passA: qubits 0-12 local in a 32KB smem tile per CTA.
// grid (8, 256): blockIdx.x = high bits 13-15, blockIdx.y = batch.
// Applies (layer>0): R0..R12, then CNOT targets 1..12.
// Applies (layer==0 INIT): analytic product state (ALL 16 R gates of layer 0
// folded into the product), then CNOT targets 1..12 only — rotations must NOT
// be re-applied in rounds 2/3. Write-only to global.
// ---------------------------------------------------------------------------
template <bool INIT>
__global__ void __launch_bounds__(256) passA_kernel(int layer) {
    __shared__ float tile[8192];
    __shared__ float sm_m[64];   // 16 gates x 4
    __shared__ float sm_p[12];
    __shared__ float tab5[32];

    const int t = threadIdx.x;
    const int s = blockIdx.x;   // bits 13-15
    const int b = blockIdx.y;

    const float* Mb = g_M + ((b * N_LAYERS + layer) * N_QUBITS) * 4;
    if (t < 64) sm_m[t] = Mb[t];
    if (t < 12) sm_p[t] = g_p[layer * 15 + t];
    if (INIT && t < 32) {
        float v = 1.0f;
        #pragma unroll
        for (int q = 0; q < 5; q++) v *= Mb[q * 4 + (((t >> q) & 1) << 1)];
        tab5[t] = v;
    }
    __syncthreads();

    const size_t gbase = (size_t)b * N_STATES + (size_t)s * 8192;
    float a[32];

    // ---- round 1: bits 0-4 local (thread base = t*32) ----
    if (INIT) {
        float f = 1.0f;
        #pragma unroll
        for (int q = 5; q < 13; q++) f *= sm_m[q * 4 + (((t >> (q - 5)) & 1) << 1)];
        #pragma unroll
        for (int q = 13; q < 16; q++) f *= sm_m[q * 4 + (((s >> (q - 13)) & 1) << 1)];
        #pragma unroll
        for (int u = 0; u < 32; u++) a[u] = f * tab5[u];
    } else {
        const float4* gp = (const float4*)(g_state + gbase + (size_t)t * 32);
        #pragma unroll
        for (int v = 0; v < 8; v++) {
            float4 x = gp[v];
            a[v * 4 + 0] = x.x; a[v * 4 + 1] = x.y;
            a[v * 4 + 2] = x.z; a[v * 4 + 3] = x.w;
        }
        // R0..R4
        #pragma unroll
        for (int q = 0; q < 5; q++) {
            float m00 = sm_m[q * 4 + 0], m01 = sm_m[q * 4 + 1];
            float m10 = sm_m[q * 4 + 2], m11 = sm_m[q * 4 + 3];
            #pragma unroll
            for (int u = 0; u < 32; u++)
                if (!((u >> q) & 1)) {
                    float a0 = a[u], a1 = a[u | (1 << q)];
                    a[u]            = m00 * a0 + m01 * a1;
                    a[u | (1 << q)] = m10 * a0 + m11 * a1;
                }
        }
    }
    // CNOT(0,1)..(3,4): ctrl bit tq-1, target bit tq (both local)
    #pragma unroll
    for (int tq = 1; tq <= 4; tq++) {
        float p = sm_p[tq - 1], omp = 1.0f - p;
        #pragma unroll
        for (int u = 0; u < 32; u++)
            if (!((u >> tq) & 1) && ((u >> (tq - 1)) & 1)) {
                float a0 = a[u], a1 = a[u | (1 << tq)];
                a[u]             = omp * a0 + p * a1;
                a[u | (1 << tq)] = omp * a1 + p * a0;
            }
    }
    #pragma unroll
    for (int u = 0; u < 32; u++) tile[PHYS(t * 32 + u)] = a[u];
    __syncthreads();

    // ---- round 2: bits 5-9 local ----
    {
        const int bl = t & 31;       // bits 0-4
        const int hi = t >> 5;       // bits 10-12
        const int base = bl + (hi << 10);
        #pragma unroll
        for (int j = 0; j < 32; j++) a[j] = tile[PHYS(base + (j << 5))];
        // R5..R9 — only when not already folded into the INIT product
        if (!INIT) {
            #pragma unroll
            for (int q = 0; q < 5; q++) {
                float m00 = sm_m[(5 + q) * 4 + 0], m01 = sm_m[(5 + q) * 4 + 1];
                float m10 = sm_m[(5 + q) * 4 + 2], m11 = sm_m[(5 + q) * 4 + 3];
                #pragma unroll
                for (int j = 0; j < 32; j++)
                    if (!((j >> q) & 1)) {
                        float a0 = a[j], a1 = a[j | (1 << q)];
                        a[j]            = m00 * a0 + m01 * a1;
                        a[j | (1 << q)] = m10 * a0 + m11 * a1;
                    }
            }
        }
        // CNOT(4,5): ctrl bit4 (uniform per thread), target bit5 = bit0(j)
        {
            float p = sm_p[4], omp = 1.0f - p;
            if ((bl >> 4) & 1) {
                #pragma unroll
                for (int j = 0; j < 32; j += 2) {
                    float a0 = a[j], a1 = a[j + 1];
                    a[j]     = omp * a0 + p * a1;
                    a[j + 1] = omp * a1 + p * a0;
                }
            }
        }
        // CNOT(5,6)..(8,9): within j bits
        #pragma unroll
        for (int tq = 1; tq <= 4; tq++) {
            float p = sm_p[4 + tq], omp = 1.0f - p;
            #pragma unroll
            for (int j = 0; j < 32; j++)
                if (!((j >> tq) & 1) && ((j >> (tq - 1)) & 1)) {
                    float a0 = a[j], a1 = a[j | (1 << tq)];
                    a[j]             = omp * a0 + p * a1;
                    a[j | (1 << tq)] = omp * a1 + p * a0;
                }
        }
        #pragma unroll
        for (int j = 0; j < 32; j++) tile[PHYS(base + (j << 5))] = a[j];
    }
    __syncthreads();

    // ---- round 3: bits 10-12 local, 4 groups of 8 per thread; store global ----
    #pragma unroll
    for (int k = 0; k < 4; k++) {
        const int g = t + (k << 8);  // bits 0-9
        float ak[8];
        #pragma unroll
        for (int j = 0; j < 8; j++) ak[j] = tile[PHYS(g + (j << 10))];
        // R10..R12 — only when not already folded into the INIT product
        if (!INIT) {
            #pragma unroll
            for (int q = 0; q < 3; q++) {
                float m00 = sm_m[(10 + q) * 4 + 0], m01 = sm_m[(10 + q) * 4 + 1];
                float m10 = sm_m[(10 + q) * 4 + 2], m11 = sm_m[(10 + q) * 4 + 3];
                #pragma unroll
                for (int j = 0; j < 8; j++)
                    if (!((j >> q) & 1)) {
                        float a0 = ak[j], a1 = ak[j | (1 << q)];
                        ak[j]            = m00 * a0 + m01 * a1;
                        ak[j | (1 << q)] = m10 * a0 + m11 * a1;
                    }
            }
        }
        // CNOT(9,10): ctrl bit9 of g (uniform), target bit10 = bit0(j)
        {
            float p = sm_p[9], omp = 1.0f - p;
            if ((g >> 9) & 1) {
                #pragma unroll
                for (int j = 0; j < 8; j += 2) {
                    float a0 = ak[j], a1 = ak[j + 1];
                    ak[j]     = omp * a0 + p * a1;
                    ak[j + 1] = omp * a1 + p * a0;
                }
            }
        }
        // CNOT(10,11): ctrl bit0(j), target bit1(j)
        {
            float p = sm_p[10], omp = 1.0f - p;
            #pragma unroll
            for (int j = 0; j < 8; j++)
                if (!((j >> 1) & 1) && (j & 1)) {
                    float a0 = ak[j], a1 = ak[j | 2];
                    ak[j]     = omp * a0 + p * a1;
                    ak[j | 2] = omp * a1 + p * a0;
                }
        }
        // CNOT(11,12): ctrl bit1(j), target bit2(j)
        {
            float p = sm_p[11], omp = 1.0f - p;
            #pragma unroll
            for (int j = 0; j < 8; j++)
                if (!((j >> 2) & 1) && ((j >> 1) & 1)) {
                    float a0 = ak[j], a1 = ak[j | 4];
                    ak[j]     = omp * a0 + p * a1;
                    ak[j | 4] = omp * a1 + p * a0;
                }
        }
        #pragma unroll
        for (int j = 0; j < 8; j++) g_state[gbase + g + (j << 10)] = ak[j];
    }
}

// ---------------------------------------------------------------------------
// passB: qubits 13-15 in registers (8 amps per thread, stride 8192).
// Applies CNOT(12,13),(13,14),(14,15) of `layer`, then (if layer<2)
// R13..R15 of layer+1 (they commute with everything in between).
// For layer==2 writes packed float32 real parts (output is a real-cast
// float32 buffer of B*N_STATES elements), bounds-guarded.
// grid (32, 256): base = blockIdx.x*256 + tid = bits 0-12, blockIdx.y = batch.
// ---------------------------------------------------------------------------
__global__ void __launch_bounds__(256) passB_kernel(int layer, float* __restrict__ outf,
                                                    long long nfloat, int as_complex) {
    const int t = threadIdx.x;
    const int base = blockIdx.x * 256 + t;  // bits 0-12
    const int b = blockIdx.y;
    const size_t gb = (size_t)b * N_STATES;

    float a[8];
    #pragma unroll
    for (int j = 0; j < 8; j++) a[j] = g_state[gb + base + (j << 13)];

    // CNOT(12,13): ctrl bit12 of base (uniform), target bit13 = bit0(j)
    {
        float p = g_p[layer * 15 + 12], omp = 1.0f - p;
        if ((base >> 12) & 1) {
            #pragma unroll
            for (int j = 0; j < 8; j += 2) {
                float a0 = a[j], a1 = a[j + 1];
                a[j]     = omp * a0 + p * a1;
                a[j + 1] = omp * a1 + p * a0;
            }
        }
    }
    // CNOT(13,14): ctrl bit0(j), target bit1(j)
    {
        float p = g_p[layer * 15 + 13], omp = 1.0f - p;
        #pragma unroll
        for (int j = 0; j < 8; j++)
            if (!((j >> 1) & 1) && (j & 1)) {
                float a0 = a[j], a1 = a[j | 2];
                a[j]     = omp * a0 + p * a1;
                a[j | 2] = omp * a1 + p * a0;
            }
    }
    // CNOT(14,15): ctrl bit1(j), target bit2(j)
    {
        float p = g_p[layer * 15 + 14], omp = 1.0f - p;
        #pragma unroll
        for (int j = 0; j < 8; j++)
            if (!((j >> 2) & 1) && ((j >> 1) & 1)) {
                float a0 = a[j], a1 = a[j | 4];
                a[j]     = omp * a0 + p * a1;
                a[j | 4] = omp * a1 + p * a0;
            }
    }

    if (layer < 2) {
        // R13..R15 of next layer
        const float* Mb = g_M + ((b * N_LAYERS + layer + 1) * N_QUBITS) * 4;
        #pragma unroll
        for (int q = 0; q < 3; q++) {
            float m00 = __ldg(Mb + (13 + q) * 4 + 0), m01 = __ldg(Mb + (13 + q) * 4 + 1);
            float m10 = __ldg(Mb + (13 + q) * 4 + 2), m11 = __ldg(Mb + (13 + q) * 4 + 3);
            #pragma unroll
            for (int j = 0; j < 8; j++)
                if (!((j >> q) & 1)) {
                    float a0 = a[j], a1 = a[j | (1 << q)];
                    a[j]            = m00 * a0 + m01 * a1;
                    a[j | (1 << q)] = m10 * a0 + m11 * a1;
                }
        }
        #pragma unroll
        for (int j = 0; j < 8; j++) g_state[gb + base + (j << 13)] = a[j];
    } else if (as_complex) {
        float2* out2 = (float2*)outf;
        #pragma unroll
        for (int j = 0; j < 8; j++) {
            long long idx = (long long)(gb + base) + ((long long)j << 13);
            if (2 * idx + 1 < nfloat) out2[idx] = make_float2(a[j], 0.0f);
        }
    } else {
        #pragma unroll
        for (int j = 0; j < 8; j++) {
            long long idx = (long long)(gb + base) + ((long long)j << 13);
            if (idx < nfloat) outf[idx] = a[j];
        }
    }
}

// ---------------------------------------------------------------------------
extern "C" void kernel_launch(void* const* d_in, const int* in_sizes, int n_in,
                              void* d_out, int out_size) {
    // Bind inputs by element count (all distinct) -> immune to metadata order.
    const float *X = nullptr, *rot = nullptr, *ent = nullptr;
    const float *W1 = nullptr, *b1 = nullptr, *W2 = nullptr, *b2 = nullptr;
    for (int i = 0; i < n_in; i++) {
        switch (in_sizes[i]) {
            case 25600: X   = (const float*)d_in[i]; break;
            case 144:   rot = (const float*)d_in[i]; break;
            case 45:    ent = (const float*)d_in[i]; break;
            case 6400:  W1  = (const float*)d_in[i]; break;
            case 64:    b1  = (const float*)d_in[i]; break;
            case 1024:  W2  = (const float*)d_in[i]; break;
            case 16:    b2  = (const float*)d_in[i]; break;
            default: break;
        }
    }
    if (!X || !rot || !ent || !W1 || !b1 || !W2 || !b2) return;

    // Output layout (confirmed R3): float32 real-cast, out_size == B*N_STATES.
    // Keep the adaptive branch as a safety net for other layouts.
    const long long NCPLX = (long long)BATCH * N_STATES;  // 16777216
    long long nfloat = (long long)out_size;
    int as_complex = ((long long)out_size >= 2 * NCPLX) ? 1 : 0;

    float* outf = (float*)d_out;

    prep_kernel<<<BATCH, 128>>>(X, rot, ent, W1, b1, W2, b2);

    dim3 gA(8, BATCH), gB(32, BATCH);
    passA_kernel<true ><<<gA, 256>>>(0);
    passB_kernel<<<gB, 256>>>(0, outf, nfloat, as_complex);
    passA_kernel<false><<<gA, 256>>>(1);
    passB_kernel<<<gB, 256>>>(1, outf, nfloat, as_complex);
    passA_kernel<false><<<gA, 256>>>(2);
    passB_kernel<<<gB, 256>>>(2, outf, nfloat, as_complex);
}

// round 6
// speedup vs baseline: 1.3950x; 1.3950x over previous
#include <cuda_runtime.h>
#include <cuda_bf16.h>
#include <math.h>

#define N_STATES 65536
#define BATCH 256

// 64 MB state scratch (real amplitudes; imaginary parts are identically zero).
__device__ float g_state[(size_t)BATCH * N_STATES];
// Fused gate matrices per (batch, layer, qubit): 8 floats
// {m00,m00',m01,m01',m10,m10',m11,m11'} where M' = C_mix * M (ctrl=1 variant).
// Layers 1,2 used; layer 0 handled analytically via g_T.
__device__ float g_MF[BATCH * 3 * 16 * 8];
// Layer-0 transfer tables per batch: [q*4 + c*2 + x], q=0 slots hold psi0(0/1).
__device__ float g_T[BATCH * 64];

// XOR swizzle so every smem access phase is bank-conflict-free.
#define PHYS(i) ((i) ^ (((i) >> 5) & 31))

// Fused gate on register window of N amps: target bit TB, ctrl bit CB (both
// compile-time bits of the register index). mf = 8 coeffs {m,m'} interleaved.
template<int N, int TB, int CB>
__device__ __forceinline__ void fgate(float* a, const float* mf) {
#pragma unroll
    for (int u = 0; u < N; u++) {
        if ((u >> TB) & 1) continue;
        const int c = (u >> CB) & 1;  // compile-time
        float a0 = a[u], a1 = a[u | (1 << TB)];
        a[u]             = fmaf(mf[0 + c], a0, mf[2 + c] * a1);
        a[u | (1 << TB)] = fmaf(mf[4 + c], a0, mf[6 + c] * a1);
    }
}

// Uniform-matrix gate (ctrl bit resolved outside, or plain rotation).
template<int N, int TB>
__device__ __forceinline__ void ugate(float* a, float m00, float m01, float m10, float m11) {
#pragma unroll
    for (int u = 0; u < N; u++) {
        if ((u >> TB) & 1) continue;
        float a0 = a[u], a1 = a[u | (1 << TB)];
        a[u]             = fmaf(m00, a0, m01 * a1);
        a[u | (1 << TB)] = fmaf(m10, a0, m11 * a1);
    }
}

// ---------------------------------------------------------------------------
// Prep: MLP -> h; fused matrices (layers 1,2); layer-0 transfer tables.
// ---------------------------------------------------------------------------
__global__ void prep_kernel(const float* __restrict__ X,
                            const float* __restrict__ rot,
                            const float* __restrict__ ent,
                            const float* __restrict__ W1,
                            const float* __restrict__ b1,
                            const float* __restrict__ W2,
                            const float* __restrict__ b2) {
    int b = blockIdx.x;
    int t = threadIdx.x;  // 128 threads
    __shared__ float sx[100];
    __shared__ float sh[64];
    __shared__ float shq[16];

    if (t < 100) sx[t] = X[b * 100 + t];
    __syncthreads();

    if (t < 64) {
        float acc = b1[t];
        #pragma unroll 4
        for (int k = 0; k < 100; k++) acc = fmaf(sx[k], W1[k * 64 + t], acc);
        sh[t] = fmaxf(acc, 0.0f);
    }
    __syncthreads();

    if (t < 16) {
        float acc = b2[t];
        #pragma unroll
        for (int j = 0; j < 64; j++) acc = fmaf(sh[j], W2[j * 16 + t], acc);
        shq[t] = tanhf(acc);
    }
    __syncthreads();

    if (t < 48) {
        int layer = t / 16, q = t % 16;
        float hv = shq[q];
        float c[3], s[3];
        #pragma unroll
        for (int i = 0; i < 3; i++) {
            float ang = rot[(layer * 16 + q) * 3 + i] * hv;
            sincosf(0.5f * ang, &s[i], &c[i]);
        }
        float m00 =  c[0] * c[1] * c[2];
        float m01 = -s[0] * s[1] * s[2];
        float m10 =  s[0] * s[1] * c[2];
        float m11 =  c[0] * c[1] * s[2];

        float p = 0.0f, omp = 1.0f;
        if (q > 0) {
            p = 1.0f / (1.0f + expf(-ent[layer * 15 + (q - 1)]));
            omp = 1.0f - p;
        }

        if (layer == 0) {
            // psi_q = column 0 of M: (m00, m10). Transfer table:
            // T_q(0,x) = psi(x);  T_q(1,x) = omp*psi(x) + p*psi(!x)
            float* T = g_T + b * 64 + q * 4;
            if (q == 0) {
                T[0] = m00; T[1] = m10; T[2] = m00; T[3] = m10;
            } else {
                T[0] = m00;               T[1] = m10;
                T[2] = omp * m00 + p * m10;
                T[3] = omp * m10 + p * m00;
            }
        } else {
            // Fused F_q = C(q-1,q) ∘ R_q: ctrl=0 -> M, ctrl=1 -> C_mix*M
            float* mf = g_MF + ((b * 3 + layer) * 16 + q) * 8;
            mf[0] = m00;  mf[2] = m01;  mf[4] = m10;  mf[6] = m11;
            mf[1] = omp * m00 + p * m10;
            mf[3] = omp * m01 + p * m11;
            mf[5] = p * m00 + omp * m10;
            mf[7] = p * m01 + omp * m11;
        }
    }
}

// ---------------------------------------------------------------------------
// Shared tail of passA-class kernels: a[32] holds amps (bits 0-4 local,
// thread t = bits 5-12, blockIdx.x = bits 13-15). Applies F_0..F_12 of the
// layer whose 13 gate-quads are in sMF (13*8 floats), via 3 smem rounds,
// then stores to g_state.
// ---------------------------------------------------------------------------
__device__ __forceinline__ void rounds_tail(float* a, float* tile,
                                            const float* sMF, int t, size_t gbase) {
    // ---- round 1: bits 0-4 local. F_0..F_4 ----
    ugate<32, 0>(a, sMF[0], sMF[2], sMF[4], sMF[6]);   // F_0 = plain R_0
    fgate<32, 1, 0>(a, sMF + 8);
    fgate<32, 2, 1>(a, sMF + 16);
    fgate<32, 3, 2>(a, sMF + 24);
    fgate<32, 4, 3>(a, sMF + 32);
    #pragma unroll
    for (int u = 0; u < 32; u++) tile[PHYS(t * 32 + u)] = a[u];
    __syncthreads();

    // ---- round 2: bits 5-9 local. F_5..F_9 ----
    {
        const int bl = t & 31;       // amp bits 0-4
        const int hi = t >> 5;       // amp bits 10-12
        const int base = bl + (hi << 10);
        #pragma unroll
        for (int j = 0; j < 32; j++) a[j] = tile[PHYS(base + (j << 5))];
        {   // F_5: ctrl = amp bit 4 (thread-uniform)
            const float* m5 = sMF + 5 * 8;
            const int c = (bl >> 4) & 1;
            ugate<32, 0>(a, m5[0 + c], m5[2 + c], m5[4 + c], m5[6 + c]);
        }
        fgate<32, 1, 0>(a, sMF + 6 * 8);
        fgate<32, 2, 1>(a, sMF + 7 * 8);
        fgate<32, 3, 2>(a, sMF + 8 * 8);
        fgate<32, 4, 3>(a, sMF + 9 * 8);
        #pragma unroll
        for (int j = 0; j < 32; j++) tile[PHYS(base + (j << 5))] = a[j];
    }
    __syncthreads();

    // ---- round 3: bits 10-12 local. F_10..F_12, store global ----
    #pragma unroll
    for (int k = 0; k < 4; k++) {
        const int g = t + (k << 8);  // amp bits 0-9
        float ak[8];
        #pragma unroll
        for (int j = 0; j < 8; j++) ak[j] = tile[PHYS(g + (j << 10))];
        {   // F_10: ctrl = amp bit 9 (uniform per g)
            const float* m10 = sMF + 10 * 8;
            const int c = (g >> 9) & 1;
            ugate<8, 0>(ak, m10[0 + c], m10[2 + c], m10[4 + c], m10[6 + c]);
        }
        fgate<8, 1, 0>(ak, sMF + 11 * 8);
        fgate<8, 2, 1>(ak, sMF + 12 * 8);
        #pragma unroll
        for (int j = 0; j < 8; j++) g_state[gbase + g + (j << 10)] = ak[j];
    }
}

// ---------------------------------------------------------------------------
// Kernel 1: generate post-layer-0 state analytically (transfer-matrix chain),
// then apply F_0..F_12 of layer 1. Write-only to global.
// amp(x) = psi0(x0) * prod_q T_q(x_{q-1}, x_q)
// grid (8, 256): blockIdx.x = bits 13-15, blockIdx.y = batch.
// ---------------------------------------------------------------------------
__global__ void __launch_bounds__(256) k_gen_l1() {
    __shared__ float tile[8192];
    __shared__ float sMF[104];
    __shared__ float sT[64];
    __shared__ float sA[32];

    const int t = threadIdx.x;
    const int s = blockIdx.x;
    const int b = blockIdx.y;

    if (t < 64) sT[t] = g_T[b * 64 + t];
    if (t < 104) sMF[t] = g_MF[((b * 3 + 1) * 16) * 8 + t];
    __syncthreads();

    if (t < 32) {
        // A(u) = psi0(u0)*T1(u0,u1)*T2(u1,u2)*T3(u2,u3)*T4(u3,u4)
        float v = sT[t & 1];
        #pragma unroll
        for (int q = 1; q <= 4; q++)
            v *= sT[q * 4 + (((t >> (q - 1)) & 1) << 1) + ((t >> q) & 1)];
        sA[t] = v;
    }
    __syncthreads();

    // Thread bits: amp bit (5+i) = bit i of t, i=0..7.
    float Bc = 1.0f;
    #pragma unroll
    for (int q = 6; q <= 12; q++)
        Bc *= sT[q * 4 + (((t >> (q - 6)) & 1) << 1) + ((t >> (q - 5)) & 1)];
    const float S = sT[13 * 4 + (((t >> 7) & 1) << 1) + (s & 1)]
                  * sT[14 * 4 + ((s & 1) << 1) + ((s >> 1) & 1)]
                  * sT[15 * 4 + (((s >> 1) & 1) << 1) + ((s >> 2) & 1)];
    const float f0 = sT[5 * 4 + 0 + (t & 1)] * Bc * S;  // T5(0, x5)
    const float f1 = sT[5 * 4 + 2 + (t & 1)] * Bc * S;  // T5(1, x5)

    float a[32];
    #pragma unroll
    for (int u = 0; u < 32; u++) a[u] = sA[u] * (((u >> 4) & 1) ? f1 : f0);

    const size_t gbase = (size_t)b * N_STATES + (size_t)s * 8192;
    rounds_tail(a, tile, sMF, t, gbase);
}

// ---------------------------------------------------------------------------
// Kernel 3: passA for layer 2 — load state, apply F_0..F_12(2), store.
// ---------------------------------------------------------------------------
__global__ void __launch_bounds__(256) k_passA_l2() {
    __shared__ float tile[8192];
    __shared__ float sMF[104];

    const int t = threadIdx.x;
    const int s = blockIdx.x;
    const int b = blockIdx.y;

    if (t < 104) sMF[t] = g_MF[((b * 3 + 2) * 16) * 8 + t];
    __syncthreads();

    const size_t gbase = (size_t)b * N_STATES + (size_t)s * 8192;
    float a[32];
    const float4* gp = (const float4*)(g_state + gbase + (size_t)t * 32);
    #pragma unroll
    for (int v = 0; v < 8; v++) {
        float4 x = gp[v];
        a[v * 4 + 0] = x.x; a[v * 4 + 1] = x.y;
        a[v * 4 + 2] = x.z; a[v * 4 + 3] = x.w;
    }
    rounds_tail(a, tile, sMF, t, gbase);
}

// ---------------------------------------------------------------------------
// passB: bits 13-15 in registers (8 amps/thread, stride 8192).
// Applies fused F_13, F_14, F_15 of `layer`. layer==2 writes the output
// (float32 real-cast, bounds-guarded; complex fallback kept).
// grid (32, 256).
// ---------------------------------------------------------------------------
__global__ void __launch_bounds__(256) k_passB(int layer, float* __restrict__ outf,
                                               long long nfloat, int as_complex) {
    const int t = threadIdx.x;
    const int base = blockIdx.x * 256 + t;  // bits 0-12
    const int b = blockIdx.y;
    const size_t gb = (size_t)b * N_STATES;

    const float* mf = g_MF + ((b * 3 + layer) * 16 + 13) * 8;

    float a[8];
    #pragma unroll
    for (int j = 0; j < 8; j++) a[j] = g_state[gb + base + (j << 13)];

    {   // F_13: ctrl = bit 12 of base (uniform), target bit13 = reg bit 0
        const int c = (base >> 12) & 1;
        ugate<8, 0>(a, __ldg(mf + 0 + c), __ldg(mf + 2 + c),
                       __ldg(mf + 4 + c), __ldg(mf + 6 + c));
    }
    fgate<8, 1, 0>(a, mf + 8);    // F_14: ctrl bit13 = reg bit0
    fgate<8, 2, 1>(a, mf + 16);   // F_15: ctrl bit14 = reg bit1

    if (layer < 2) {
        #pragma unroll
        for (int j = 0; j < 8; j++) g_state[gb + base + (j << 13)] = a[j];
    } else if (as_complex) {
        float2* out2 = (float2*)outf;
        #pragma unroll
        for (int j = 0; j < 8; j++) {
            long long idx = (long long)(gb + base) + ((long long)j << 13);
            if (2 * idx + 1 < nfloat) out2[idx] = make_float2(a[j], 0.0f);
        }
    } else {
        #pragma unroll
        for (int j = 0; j < 8; j++) {
            long long idx = (long long)(gb + base) + ((long long)j << 13);
            if (idx < nfloat) outf[idx] = a[j];
        }
    }
}

// ---------------------------------------------------------------------------
extern "C" void kernel_launch(void* const* d_in, const int* in_sizes, int n_in,
                              void* d_out, int out_size) {
    // Bind inputs by element count (all distinct) -> immune to metadata order.
    const float *X = nullptr, *rot = nullptr, *ent = nullptr;
    const float *W1 = nullptr, *b1 = nullptr, *W2 = nullptr, *b2 = nullptr;
    for (int i = 0; i < n_in; i++) {
        switch (in_sizes[i]) {
            case 25600: X   = (const float*)d_in[i]; break;
            case 144:   rot = (const float*)d_in[i]; break;
            case 45:    ent = (const float*)d_in[i]; break;
            case 6400:  W1  = (const float*)d_in[i]; break;
            case 64:    b1  = (const float*)d_in[i]; break;
            case 1024:  W2  = (const float*)d_in[i]; break;
            case 16:    b2  = (const float*)d_in[i]; break;
            default: break;
        }
    }
    if (!X || !rot || !ent || !W1 || !b1 || !W2 || !b2) return;

    const long long NCPLX = (long long)BATCH * N_STATES;  // 16777216
    long long nfloat = (long long)out_size;
    int as_complex = ((long long)out_size >= 2 * NCPLX) ? 1 : 0;
    float* outf = (float*)d_out;

    prep_kernel<<<BATCH, 128>>>(X, rot, ent, W1, b1, W2, b2);

    dim3 gA(8, BATCH), gB(32, BATCH);
    k_gen_l1<<<gA, 256>>>();                            // layer0 analytic + F0-12(1)
    k_passB<<<gB, 256>>>(1, outf, nfloat, as_complex);  // F13-15(1)
    k_passA_l2<<<gA, 256>>>();                          // F0-12(2)
    k_passB<<<gB, 256>>>(2, outf, nfloat, as_complex);  // F13-15(2) + output
}

// round 10
// speedup vs baseline: 4.0522x; 2.9049x over previous
#include <cuda_runtime.h>
#include <cuda_bf16.h>
#include <math.h>

#define N_STATES 65536
#define BATCH 256

// Per-batch MPS site data, 304 floats apart:
//  [ (q-2)*20 for q=2..14 ]: B1[l1*2+r1](4)  B2[l2*4+r2*2+r1](8)  B3[l3*4+x*2+r2](8)
//  [260]: w15[x*8 + (l1 + 2*l2 + 4*l3)]  (16)
//  [276]: r01[(x1*2+x0)*4 + (r1 + 2*r2)] (16)
#define W_STRIDE 304
__device__ float g_W[BATCH * W_STRIDE];

// ---------------------------------------------------------------------------
// Prep: MLP -> h -> rotation matrices M^l_q and CNOT probs p^l_q ->
// MPS site tensors (structured factors) per batch.
// B^{l,0} = M ; B^{l,1}[i,j] = (1-p^l_{q-1}) M[i,j] + p^l_{q-1} M[1-i,j]
// ---------------------------------------------------------------------------
__device__ __forceinline__ float bgf(const float* M, float p, int l, int i, int j) {
    float v = M[i * 2 + j];
    if (l) v = (1.0f - p) * v + p * M[(1 - i) * 2 + j];
    return v;
}

__global__ void prep_kernel(const float* __restrict__ X,
                            const float* __restrict__ rot,
                            const float* __restrict__ ent,
                            const float* __restrict__ W1,
                            const float* __restrict__ b1,
                            const float* __restrict__ W2,
                            const float* __restrict__ b2) {
    int b = blockIdx.x;
    int t = threadIdx.x;  // 128 threads
    __shared__ float sx[100];
    __shared__ float sh[64];
    __shared__ float shq[16];
    __shared__ float sM[3][16][4];   // row-major 2x2: m00,m01,m10,m11
    __shared__ float sp[3][15];

    if (t < 100) sx[t] = X[b * 100 + t];
    __syncthreads();

    if (t < 64) {
        float acc = b1[t];
        #pragma unroll 4
        for (int k = 0; k < 100; k++) acc = fmaf(sx[k], W1[k * 64 + t], acc);
        sh[t] = fmaxf(acc, 0.0f);
    }
    __syncthreads();

    if (t < 16) {
        float acc = b2[t];
        #pragma unroll
        for (int j = 0; j < 64; j++) acc = fmaf(sh[j], W2[j * 16 + t], acc);
        shq[t] = tanhf(acc);
    }
    __syncthreads();

    if (t < 48) {
        int layer = t / 16, q = t % 16;
        float hv = shq[q];
        float c[3], s[3];
        #pragma unroll
        for (int i = 0; i < 3; i++) {
            float ang = rot[(layer * 16 + q) * 3 + i] * hv;
            sincosf(0.5f * ang, &s[i], &c[i]);
        }
        sM[layer][q][0] =  c[0] * c[1] * c[2];   // m00
        sM[layer][q][1] = -s[0] * s[1] * s[2];   // m01
        sM[layer][q][2] =  s[0] * s[1] * c[2];   // m10
        sM[layer][q][3] =  c[0] * c[1] * s[2];   // m11
    }
    if (t >= 48 && t < 93) {  // 45 probs
        int i = t - 48;
        sp[i / 15][i % 15] = 1.0f / (1.0f + expf(-ent[i]));
    }
    __syncthreads();

    float* Wb = g_W + b * W_STRIDE;

    if (t >= 2 && t <= 14) {
        // Site q = t: 20 structured coefficients
        int q = t;
        float* o = Wb + (q - 2) * 20;
        float p1 = sp[0][q - 1], p2 = sp[1][q - 1], p3 = sp[2][q - 1];
        const float* M1 = sM[0][q];
        const float* M2 = sM[1][q];
        const float* M3 = sM[2][q];
        #pragma unroll
        for (int l = 0; l < 2; l++)
            #pragma unroll
            for (int r1 = 0; r1 < 2; r1++)
                o[l * 2 + r1] = bgf(M1, p1, l, r1, 0);                 // B1[l][r1]
        #pragma unroll
        for (int l = 0; l < 2; l++)
            #pragma unroll
            for (int r2 = 0; r2 < 2; r2++)
                #pragma unroll
                for (int r1 = 0; r1 < 2; r1++)
                    o[4 + l * 4 + r2 * 2 + r1] = bgf(M2, p2, l, r2, r1); // B2[l][r2][r1]
        #pragma unroll
        for (int l = 0; l < 2; l++)
            #pragma unroll
            for (int x = 0; x < 2; x++)
                #pragma unroll
                for (int r2 = 0; r2 < 2; r2++)
                    o[12 + l * 4 + x * 2 + r2] = bgf(M3, p3, l, x, r2);  // B3[l][x][r2]
    }

    if (t == 15) {
        // w15[x][l1,l2,l3] = (B3_{l3} B2_{l2} B1_{l1})[x,0]  at site 15
        float p1 = sp[0][14], p2 = sp[1][14], p3 = sp[2][14];
        const float* M1 = sM[0][15];
        const float* M2 = sM[1][15];
        const float* M3 = sM[2][15];
        for (int x = 0; x < 2; x++)
            for (int l3 = 0; l3 < 2; l3++)
                for (int l2 = 0; l2 < 2; l2++)
                    for (int l1 = 0; l1 < 2; l1++) {
                        float acc = 0.0f;
                        for (int i = 0; i < 2; i++)
                            for (int j = 0; j < 2; j++)
                                acc += bgf(M3, p3, l3, x, i) *
                                       bgf(M2, p2, l2, i, j) *
                                       bgf(M1, p1, l1, j, 0);
                        Wb[260 + x * 8 + (l1 + 2 * l2 + 4 * l3)] = acc;
                    }
    }

    if (t == 16) {
        // r01[x0,x1][r1,r2] = sum_{l1,l2} M1_0[l1,0] M2_0[l2,l1] M3_0[x0,l2]
        //                     * B1_1^{l1}[r1,0] * B2_1^{l2}[r2,r1] * B3_1^{x0}[x1,r2]
        float p1 = sp[0][0], p2 = sp[1][0], p3 = sp[2][0];
        const float* N1 = sM[0][0];  // site 0 rotations
        const float* N2 = sM[1][0];
        const float* N3 = sM[2][0];
        const float* M1 = sM[0][1];  // site 1 rotations
        const float* M2 = sM[1][1];
        const float* M3 = sM[2][1];
        for (int x1 = 0; x1 < 2; x1++)
            for (int x0 = 0; x0 < 2; x0++)
                for (int r2 = 0; r2 < 2; r2++)
                    for (int r1 = 0; r1 < 2; r1++) {
                        float acc = 0.0f;
                        for (int l1 = 0; l1 < 2; l1++)
                            for (int l2 = 0; l2 < 2; l2++)
                                acc += N1[l1 * 2 + 0] * N2[l2 * 2 + l1] * N3[x0 * 2 + l2]
                                     * bgf(M1, p1, l1, r1, 0)
                                     * bgf(M2, p2, l2, r2, r1)
                                     * bgf(M3, p3, x0, x1, r2);
                        Wb[276 + (x1 * 2 + x0) * 4 + (r1 + 2 * r2)] = acc;
                    }
    }
}

// ---------------------------------------------------------------------------
// Structured site-tensor matvec: u'[l1+2l2+4l3] =
//   sum_{r1,r2} B1[l1][r1] * B2[l2][r2,r1] * B3[l3][x,r2] * u[r1+2r2+4x]
// 40 FLOPs instead of dense 8x8 = 128.
// ---------------------------------------------------------------------------
__device__ __forceinline__ void site_mv(const float* __restrict__ sW, int q, int x,
                                        const float* __restrict__ u,
                                        float* __restrict__ uo) {
    const float* B  = sW + (q - 2) * 20;
    const float* B2 = B + 4;
    const float* B3 = B + 12;
    // stage A: va[l3*4 + r2*2 + r1] = B3[l3][x][r2] * u[r1 + 2 r2 + 4 x]
    float va[8];
    #pragma unroll
    for (int l3 = 0; l3 < 2; l3++)
        #pragma unroll
        for (int r2 = 0; r2 < 2; r2++) {
            float c = B3[l3 * 4 + x * 2 + r2];
            #pragma unroll
            for (int r1 = 0; r1 < 2; r1++)
                va[l3 * 4 + r2 * 2 + r1] = c * u[r1 + 2 * r2 + 4 * x];
        }
    // stage B: vb[l3*4 + l2*2 + r1] = sum_{r2} B2[l2][r2][r1] * va[l3*4 + r2*2 + r1]
    float vb[8];
    #pragma unroll
    for (int l3 = 0; l3 < 2; l3++)
        #pragma unroll
        for (int l2 = 0; l2 < 2; l2++)
            #pragma unroll
            for (int r1 = 0; r1 < 2; r1++)
                vb[l3 * 4 + l2 * 2 + r1] =
                    fmaf(B2[l2 * 4 + 2 + r1], va[l3 * 4 + 2 + r1],
                         B2[l2 * 4 + 0 + r1] * va[l3 * 4 + 0 + r1]);
    // stage C: uo[l1 + 2 l2 + 4 l3] = sum_{r1} B1[l1][r1] * vb[l3*4 + l2*2 + r1]
    #pragma unroll
    for (int l3 = 0; l3 < 2; l3++)
        #pragma unroll
        for (int l2 = 0; l2 < 2; l2++)
            #pragma unroll
            for (int l1 = 0; l1 < 2; l1++)
                uo[l1 + 2 * l2 + 4 * l3] =
                    fmaf(B[l1 * 2 + 1], vb[l3 * 4 + l2 * 2 + 1],
                         B[l1 * 2 + 0] * vb[l3 * 4 + l2 * 2 + 0]);
}

// ---------------------------------------------------------------------------
// Main kernel: one thread computes 32 amplitudes directly from the MPS.
// grid (8, 256): blockIdx.x = bits 13-15, blockIdx.y = batch. 256 threads:
// t = amp bits 5-12. Register loop covers bits 0-4.
// ---------------------------------------------------------------------------
__global__ void __launch_bounds__(256) mps_kernel(float* __restrict__ outf,
                                                  long long nfloat, int as_complex) {
    __shared__ float sW[292];
    const int t = threadIdx.x;
    const int s = blockIdx.x;
    const int b = blockIdx.y;

    {
        const float* Wb = g_W + b * W_STRIDE;
        sW[t < 292 ? t : 0] = Wb[t < 292 ? t : 0];
        int t2 = t + 256;
        if (t2 < 292) sW[t2] = Wb[t2];
    }
    __syncthreads();

    // Prefix: sites 15 (table), 14, 13  (x13..x15 = bits of s)
    float u[8], u2[8];
    {
        const int x15 = (s >> 2) & 1;
        #pragma unroll
        for (int i = 0; i < 8; i++) u[i] = sW[260 + x15 * 8 + i];
        site_mv(sW, 14, (s >> 1) & 1, u, u2);
        site_mv(sW, 13, s & 1, u2, u);
    }
    // Mid: sites 12..5 from thread bits 7..0
    #pragma unroll
    for (int q = 12; q >= 5; q -= 2) {
        site_mv(sW, q,     (t >> (q - 5)) & 1, u, u2);
        site_mv(sW, q - 1, (t >> (q - 6)) & 1, u2, u);
    }

    // Tail: expand sites 4,3,2 and contract with r01.
    float a4[2][8];
    site_mv(sW, 4, 0, u, a4[0]);
    site_mv(sW, 4, 1, u, a4[1]);

    const long long slab = (long long)b * N_STATES + (long long)s * 8192 + (long long)t * 32;

    #pragma unroll
    for (int x4 = 0; x4 < 2; x4++)
        #pragma unroll
        for (int x3 = 0; x3 < 2; x3++) {
            float a3[8];
            site_mv(sW, 3, x3, a4[x4], a3);
            float vals[8];
            #pragma unroll
            for (int x2 = 0; x2 < 2; x2++) {
                float a2[8];
                site_mv(sW, 2, x2, a3, a2);
                #pragma unroll
                for (int x1 = 0; x1 < 2; x1++)
                    #pragma unroll
                    for (int x0 = 0; x0 < 2; x0++) {
                        const float* r = sW + 276 + (x1 * 2 + x0) * 4;
                        float acc =             r[0] * a2[0 + 4 * x1];
                        acc = fmaf(r[1], a2[1 + 4 * x1], acc);
                        acc = fmaf(r[2], a2[2 + 4 * x1], acc);
                        acc = fmaf(r[3], a2[3 + 4 * x1], acc);
                        vals[x0 + 2 * x1 + 4 * x2] = acc;
                    }
            }
            const long long off = slab + 8 * (x3 + 2 * x4);
            if (!as_complex) {
                if (off + 7 < nfloat) {
                    float4* o4 = (float4*)(outf + off);
                    o4[0] = make_float4(vals[0], vals[1], vals[2], vals[3]);
                    o4[1] = make_float4(vals[4], vals[5], vals[6], vals[7]);
                } else {
                    #pragma unroll
                    for (int j = 0; j < 8; j++)
                        if (off + j < nfloat) outf[off + j] = vals[j];
                }
            } else {
                float2* o2 = (float2*)outf;
                #pragma unroll
                for (int j = 0; j < 8; j++)
                    if (2 * (off + j) + 1 < nfloat)
                        o2[off + j] = make_float2(vals[j], 0.0f);
            }
        }
}

// ---------------------------------------------------------------------------
extern "C" void kernel_launch(void* const* d_in, const int* in_sizes, int n_in,
                              void* d_out, int out_size) {
    // Bind inputs by element count (all distinct) -> immune to metadata order.
    const float *X = nullptr, *rot = nullptr, *ent = nullptr;
    const float *W1 = nullptr, *b1 = nullptr, *W2 = nullptr, *b2 = nullptr;
    for (int i = 0; i < n_in; i++) {
        switch (in_sizes[i]) {
            case 25600: X   = (const float*)d_in[i]; break;
            case 144:   rot = (const float*)d_in[i]; break;
            case 45:    ent = (const float*)d_in[i]; break;
            case 6400:  W1  = (const float*)d_in[i]; break;
            case 64:    b1  = (const float*)d_in[i]; break;
            case 1024:  W2  = (const float*)d_in[i]; break;
            case 16:    b2  = (const float*)d_in[i]; break;
            default: break;
        }
    }
    if (!X || !rot || !ent || !W1 || !b1 || !W2 || !b2) return;

    const long long NCPLX = (long long)BATCH * N_STATES;  // 16777216
    long long nfloat = (long long)out_size;
    int as_complex = ((long long)out_size >= 2 * NCPLX) ? 1 : 0;
    float* outf = (float*)d_out;

    prep_kernel<<<BATCH, 128>>>(X, rot, ent, W1, b1, W2, b2);
    dim3 g(8, BATCH);
    mps_kernel<<<g, 256>>>(outf, nfloat, as_complex);
}